// round 17
// baseline (speedup 1.0000x reference)
#include <cuda_runtime.h>
#include <cuda_bf16.h>
#include <stdint.h>

#define NATOMS 4096
#define DD     352     // 128 + 128 + 96
#define H      256
#define SEL    128
#define ASEL   16

#define R2SEL  132.25f   // 11.5^2  primary collect radius^2
#define R2BIG  182.25f   // 13.5^2  fallback radius^2
#define HB     128       // trim histogram bins
#define BINSC  (128.0f / 182.26f)
#define ZBINS  64
#define ZW     (40.0f / 64.0f)
#define CAP4   768       // candidate capacity per atom

#define TPT    73        // tiles per type in k_mlp grid (32 atoms/tile)
#define NBLK   (2 * TPT)

// ---------------- scratch (no allocations allowed) ----------------
__device__ int      g_cnt[2];
__device__ int      g_zcnt[ZBINS];
__device__ unsigned g_binrank[NATOMS];   // (zbin<<16)|rank
__device__ int      g_list[2 * NATOMS];
__device__ unsigned g_typemask[NATOMS / 32];
__device__ float4   g_xyz4[NATOMS];      // by original index
__device__ float4   g_xyzz[NATOMS];      // z-sorted; .w = original index bits
__device__ int      g_zstart[ZBINS];
__device__ float    g_desc[(size_t)NATOMS * DD];
__device__ float    g_bsum[NBLK];
__device__ int      g_done;              // zero-init; self-resetting

// pre-split weights, chunked [t][kchunk][n][16], bf16 hi/lo
#define NC1 22            // 352/16
#define NC2 16            // 256/16
__device__ __nv_bfloat16 g_w1h[2 * NC1 * H * 16];
__device__ __nv_bfloat16 g_w1l[2 * NC1 * H * 16];
__device__ __nv_bfloat16 g_w2h[2 * NC2 * H * 16];
__device__ __nv_bfloat16 g_w2l[2 * NC2 * H * 16];
__device__ __nv_bfloat16 g_w3h[2 * NC2 * H * 16];
__device__ __nv_bfloat16 g_w3l[2 * NC2 * H * 16];

// ---------------- helpers ----------------
__device__ __forceinline__ float key_dist(unsigned long long k) {
    return __uint_as_float((unsigned)((k >> 12) & 0x7FFFFFFFull));
}
__device__ __forceinline__ int key_idx(unsigned long long k) {
    return (int)(k & 0xFFFull);
}
__device__ __forceinline__ void dm_vec4(float xi, float yi, float zi,
                                        int j,
                                        float bx, float by, float bz,
                                        float ibx, float iby, float ibz,
                                        float& dx, float& dy, float& dz) {
    float4 p = g_xyz4[j];
    dx = xi - p.x + 1e-16f;
    dy = yi - p.y + 1e-16f;
    dz = zi - p.z + 1e-16f;
    dx -= bx * rintf(dx * ibx);
    dy -= by * rintf(dy * iby);
    dz -= bz * rintf(dz * ibz);
}
__device__ __forceinline__ unsigned long long u64min(unsigned long long a, unsigned long long b) {
    return a < b ? a : b;
}
__device__ __forceinline__ unsigned long long u64max(unsigned long long a, unsigned long long b) {
    return a > b ? a : b;
}
__device__ __forceinline__ uint32_t smem_u32(const void* p) {
    return (uint32_t)__cvta_generic_to_shared(p);
}
__device__ __forceinline__ void ldsm4(uint32_t (&r)[4], const void* p) {
    asm volatile("ldmatrix.sync.aligned.m8n8.x4.shared.b16 {%0,%1,%2,%3}, [%4];"
                 : "=r"(r[0]), "=r"(r[1]), "=r"(r[2]), "=r"(r[3]) : "r"(smem_u32(p)));
}
__device__ __forceinline__ void ldsm4a(uint32_t (&r)[4], uint32_t addr) {
    asm volatile("ldmatrix.sync.aligned.m8n8.x4.shared.b16 {%0,%1,%2,%3}, [%4];"
                 : "=r"(r[0]), "=r"(r[1]), "=r"(r[2]), "=r"(r[3]) : "r"(addr));
}
__device__ __forceinline__ void cp16(uint32_t dst, const void* src) {
    asm volatile("cp.async.cg.shared.global [%0], [%1], 16;" :: "r"(dst), "l"(src));
}
__device__ __forceinline__ void cp_commit() {
    asm volatile("cp.async.commit_group;");
}
__device__ __forceinline__ void cp_wait2() {
    asm volatile("cp.async.wait_group 2;");
}
__device__ __forceinline__ void cp_wait0() {
    asm volatile("cp.async.wait_group 0;");
}
__device__ __forceinline__ void mma_bf16s(float (&d)[4], const uint32_t (&a)[4],
                                          uint32_t b0, uint32_t b1) {
    asm volatile("mma.sync.aligned.m16n8k16.row.col.f32.bf16.bf16.f32 "
                 "{%0,%1,%2,%3},{%4,%5,%6,%7},{%8,%9},{%0,%1,%2,%3};"
                 : "+f"(d[0]), "+f"(d[1]), "+f"(d[2]), "+f"(d[3])
                 : "r"(a[0]), "r"(a[1]), "r"(a[2]), "r"(a[3]), "r"(b0), "r"(b1));
}
// exact-form fast tanh: 1 - 2/(e^{2|x|}+1), sign restored
__device__ __forceinline__ float tanh_fast(float x) {
    float ax = fabsf(x);
    float e  = __expf(2.0f * ax);
    float r  = 1.0f - 2.0f / (e + 1.0f);
    return copysignf(r, x);
}
__device__ __forceinline__ void split_store(__nv_bfloat16* Ahi, __nv_bfloat16* Alo,
                                            int m, int n, float v0, float v1) {
    __nv_bfloat16 h0 = __float2bfloat16(v0);
    __nv_bfloat16 h1 = __float2bfloat16(v1);
    __nv_bfloat16 l0 = __float2bfloat16(v0 - __bfloat162float(h0));
    __nv_bfloat16 l1 = __float2bfloat16(v1 - __bfloat162float(h1));
    *(__nv_bfloat162*)(Ahi + m * 264 + n) = __nv_bfloat162(h0, h1);
    *(__nv_bfloat162*)(Alo + m * 264 + n) = __nv_bfloat162(l0, l1);
}
__device__ __forceinline__ uint32_t swz16(uint32_t u) {
    return u ^ ((u >> 3) & 1u);
}

// ---------------- k_binA: 16 blocks, parallel binning + type lists ----------------
__global__ void __launch_bounds__(256) k_binA(const int* __restrict__ types,
                                              const float* __restrict__ xyz) {
    const int i    = blockIdx.x * 256 + threadIdx.x;
    const int lane = threadIdx.x & 31;

    float x = xyz[3 * i], y = xyz[3 * i + 1], z = xyz[3 * i + 2];
    int t = types[i];
    g_xyz4[i] = make_float4(x, y, z, 0.0f);

    int b = min((int)(z * (1.0f / ZW)), ZBINS - 1);
    int rank = atomicAdd(&g_zcnt[b], 1);
    g_binrank[i] = ((unsigned)b << 16) | (unsigned)rank;

    // warp-aggregated type-list placement
    unsigned m1 = __ballot_sync(0xFFFFFFFFu, t == 1);
    unsigned m0 = ~m1;
    int pre1 = __popc(m1 & ((1u << lane) - 1));
    int pre0 = __popc(m0 & ((1u << lane) - 1));
    int base0 = 0, base1 = 0;
    if (lane == 0) {
        int n1 = __popc(m1);
        if (n1)      base1 = atomicAdd(&g_cnt[1], n1);
        if (32 - n1) base0 = atomicAdd(&g_cnt[0], 32 - n1);
    }
    base0 = __shfl_sync(0xFFFFFFFFu, base0, 0);
    base1 = __shfl_sync(0xFFFFFFFFu, base1, 0);
    if (t) g_list[NATOMS + base1 + pre1] = i;
    else   g_list[base0 + pre0] = i;

    unsigned wm = __ballot_sync(0xFFFFFFFFu, t == 1);
    if (lane == 0 && wm) atomicOr(&g_typemask[i >> 5], wm);
}

// ---------------- k_binB: scan + scatter ----------------
__global__ void __launch_bounds__(1024) k_binB() {
    __shared__ int zs[ZBINS];
    const int tid  = threadIdx.x;
    const int lane = tid & 31, wrp = tid >> 5;

    if (wrp == 0) {
        int v0 = g_zcnt[lane], v1 = g_zcnt[32 + lane];
        int s0 = v0, s1 = v1;
        #pragma unroll
        for (int o = 1; o < 32; o <<= 1) {
            int n0 = __shfl_up_sync(0xFFFFFFFFu, s0, o);
            int n1 = __shfl_up_sync(0xFFFFFFFFu, s1, o);
            if (lane >= o) { s0 += n0; s1 += n1; }
        }
        int tot0 = __shfl_sync(0xFFFFFFFFu, s0, 31);
        int e0 = s0 - v0, e1 = tot0 + s1 - v1;
        zs[lane] = e0;        g_zstart[lane] = e0;
        zs[32 + lane] = e1;   g_zstart[32 + lane] = e1;
    }
    __syncthreads();

    #pragma unroll
    for (int a = 0; a < 4; a++) {
        int i = tid * 4 + a;
        unsigned br = g_binrank[i];
        int b = (int)(br >> 16), rank = (int)(br & 0xFFFFu);
        float4 p = g_xyz4[i];
        g_xyzz[zs[b] + rank] = make_float4(p.x, p.y, p.z, __int_as_float(i));
    }
}

// ---------------- descriptor kernel: 4 z-adjacent atoms per block (unchanged) ----------------
__global__ void __launch_bounds__(256) k_desc(const float* __restrict__ box,
                                              const float* __restrict__ w1,
                                              const float* __restrict__ w2,
                                              const float* __restrict__ w3) {
    __shared__ unsigned long long cand[4][CAP4];
    __shared__ unsigned long long sb[4][2][256];
    __shared__ int      hist[4][2][HB];
    __shared__ unsigned tmask[NATOMS / 32];
    __shared__ int      s_zs[ZBINS];
    __shared__ int      s_total[4], s_flag, s_cut[4][2], s_pos[4][2];
    __shared__ float    sA[4][9];

    const int blk  = blockIdx.x;
    const int tid  = threadIdx.x;
    const int lane = tid & 31, wrp = tid >> 5;
    const float bx = box[0], by = box[1], bz = box[2];
    const float ibx = 1.0f / bx, iby = 1.0f / by, ibz = 1.0f / bz;

    float cx[4], cy[4], cz[4];
    int   ci[4];
    #pragma unroll
    for (int a = 0; a < 4; a++) {
        float4 c = g_xyzz[blk * 4 + a];
        cx[a] = c.x; cy[a] = c.y; cz[a] = c.z;
        ci[a] = __float_as_int(c.w);
    }
    const int zb0 = min((int)(cz[0] * (1.0f / ZW)), ZBINS - 1);
    const int zb3 = min((int)(cz[3] * (1.0f / ZW)), ZBINS - 1);

    if (tid < NATOMS / 32) tmask[tid] = g_typemask[tid];
    if (tid < ZBINS) s_zs[tid] = g_zstart[tid];
    if (tid == 0) s_flag = 1;
    __syncthreads();

    for (int attempt = 0; attempt < 3 && s_flag; attempt++) {
        __syncthreads();
        if (tid < 4) s_total[tid] = 0;
        if (tid == 0) s_flag = 0;
        for (int h = tid; h < 4 * 2 * HB; h += 256) ((int*)hist)[h] = 0;
        __syncthreads();

        const float rc2 = (attempt == 0) ? R2SEL : R2BIG;
        int start, cntj;
        if (attempt < 2) {
            int NB = (attempt == 0) ? 19 : 22;
            int span = (zb3 - zb0) + 2 * NB + 1;
            if (span >= ZBINS) { start = 0; cntj = NATOMS; }
            else {
                int lo = (zb0 - NB) & (ZBINS - 1);
                int hi = (zb3 + NB + 1) & (ZBINS - 1);
                start = s_zs[lo];
                cntj  = (s_zs[hi] - start + NATOMS) & (NATOMS - 1);
            }
        } else {
            start = 0; cntj = NATOMS;
        }
        const int kmax = (cntj + 255) & ~255;

        for (int k = tid; k < kmax; k += 256) {
            bool inb = (k < cntj);
            int idx = start + (inb ? k : 0);
            if (idx >= NATOMS) idx -= NATOMS;
            float4 pj = g_xyzz[idx];
            int j = __float_as_int(pj.w);
            unsigned t = (tmask[j >> 5] >> (j & 31)) & 1u;

            #pragma unroll
            for (int a = 0; a < 4; a++) {
                float dx = cx[a] - pj.x + 1e-16f;
                float dy = cy[a] - pj.y + 1e-16f;
                float dz = cz[a] - pj.z + 1e-16f;
                dx -= bx * rintf(dx * ibx);
                dy -= by * rintf(dy * iby);
                dz -= bz * rintf(dz * ibz);
                float d2 = dx * dx + dy * dy + dz * dz;
                bool take = inb && (j != ci[a]) && (d2 < rc2);
                unsigned m = __ballot_sync(0xFFFFFFFFu, take);
                int pre = __popc(m & ((1u << lane) - 1));
                int basep = 0;
                if (lane == 0 && m) basep = atomicAdd(&s_total[a], __popc(m));
                basep = __shfl_sync(0xFFFFFFFFu, basep, 0);
                if (take && basep + pre < CAP4)
                    cand[a][basep + pre] = (((unsigned long long)__float_as_uint(d2)) << 13)
                                         | ((unsigned long long)t << 12) | (unsigned)j;
            }
        }
        __syncthreads();

        #pragma unroll
        for (int a = 0; a < 4; a++) {
            int total = min(s_total[a], CAP4);
            for (int c = tid; c < total; c += 256) {
                unsigned long long e = cand[a][c];
                int t = (int)((e >> 12) & 1ull);
                float d2 = __uint_as_float((unsigned)(e >> 13));
                int b = min((int)(d2 * BINSC), HB - 1);
                atomicAdd(&hist[a][t][b], 1);
            }
        }
        __syncthreads();

        {
            int a = wrp >> 1, t = wrp & 1;
            int carry = 0, cut = HB - 1;
            #pragma unroll
            for (int c = 0; c < HB / 32; c++) {
                int b = c * 32 + lane;
                int v = hist[a][t][b];
                int orig = v;
                #pragma unroll
                for (int o = 1; o < 32; o <<= 1) {
                    int n = __shfl_up_sync(0xFFFFFFFFu, v, o);
                    if (lane >= o) v += n;
                }
                v += carry;
                int prev = v - orig;
                if (prev < SEL && v >= SEL) cut = b;
                carry = __shfl_sync(0xFFFFFFFFu, v, 31);
            }
            #pragma unroll
            for (int o = 16; o; o >>= 1) cut = min(cut, __shfl_xor_sync(0xFFFFFFFFu, cut, o));
            if (lane == 0) {
                s_cut[a][t] = cut;
                if (carry < SEL) atomicExch(&s_flag, 1);
            }
        }
        __syncthreads();
    }

    if (tid < 8) s_pos[tid >> 1][tid & 1] = 0;
    {
        unsigned long long* sbl = &sb[0][0][0];
        for (int s = tid; s < 8 * 256; s += 256) sbl[s] = ~0ull;
    }
    __syncthreads();

    #pragma unroll
    for (int a = 0; a < 4; a++) {
        int total = min(s_total[a], CAP4);
        int cut0 = s_cut[a][0], cut1 = s_cut[a][1];
        for (int c = tid; c < total; c += 256) {
            unsigned long long e = cand[a][c];
            int t = (int)((e >> 12) & 1ull);
            float d2 = __uint_as_float((unsigned)(e >> 13));
            int b = min((int)(d2 * BINSC), HB - 1);
            if (b <= (t ? cut1 : cut0)) {
                int pos = atomicAdd(&s_pos[a][t], 1);
                if (pos < 256) {
                    float d = sqrtf(d2);
                    sb[a][t][pos] = (((unsigned long long)__float_as_uint(d)) << 12) | (e & 0xFFFull);
                }
            }
        }
    }
    __syncthreads();

    {
        unsigned long long kk[8];
        #pragma unroll
        for (int q = 0; q < 8; q++) kk[q] = sb[q >> 1][q & 1][tid];
        #pragma unroll
        for (int k = 2; k <= 256; k <<= 1) {
            #pragma unroll
            for (int j = k >> 1; j > 0; j >>= 1) {
                bool up  = ((tid & k) == 0);
                bool low = ((tid & j) == 0);
                bool km  = (low == up);
                unsigned long long oo[8];
                if (j >= 32) {
                    #pragma unroll
                    for (int q = 0; q < 8; q++) sb[q >> 1][q & 1][tid] = kk[q];
                    __syncthreads();
                    #pragma unroll
                    for (int q = 0; q < 8; q++) oo[q] = sb[q >> 1][q & 1][tid ^ j];
                    __syncthreads();
                } else {
                    #pragma unroll
                    for (int q = 0; q < 8; q++)
                        oo[q] = __shfl_xor_sync(0xFFFFFFFFu, kk[q], j);
                }
                #pragma unroll
                for (int q = 0; q < 8; q++)
                    kk[q] = km ? u64min(kk[q], oo[q]) : u64max(kk[q], oo[q]);
            }
        }
        #pragma unroll
        for (int q = 0; q < 8; q++) sb[q >> 1][q & 1][tid] = kk[q];
    }
    __syncthreads();

    #pragma unroll
    for (int q = 0; q < 2; q++) {
        int a = (tid >> 7) + 2 * q, s = tid & 127;
        float* dsc = g_desc + (size_t)ci[a] * DD;
        dsc[s]       = 1.0f / (key_dist(sb[a][0][s]) + 1e-16f);
        dsc[SEL + s] = 1.0f / (key_dist(sb[a][1][s]) + 1e-16f);
    }

    if ((tid & 63) == 0) {
        int a = tid >> 6;
        float xc = cx[a], yc = cy[a], zc = cz[a];
        float d00 = key_dist(sb[a][0][0]), d01 = key_dist(sb[a][0][1]);
        float d10 = key_dist(sb[a][1][0]), d11 = key_dist(sb[a][1][1]);
        int   j00 = key_idx(sb[a][0][0]),  j01 = key_idx(sb[a][0][1]);
        int   j10 = key_idx(sb[a][1][0]),  j11 = key_idx(sb[a][1][1]);

        float lfd0, lfd1; int lfi0, lfi1;
        if (d10 < d00) {
            lfd0 = d10; lfi0 = j10;
            if (d11 < d00) { lfd1 = d11; lfi1 = j11; }
            else           { lfd1 = d00; lfi1 = j00; }
        } else {
            lfd0 = d00; lfi0 = j00;
            if (d10 < d01) { lfd1 = d10; lfi1 = j10; }
            else           { lfd1 = d01; lfi1 = j01; }
        }

        float ax, ay, az, bx2, by2, bz2;
        dm_vec4(xc, yc, zc, lfi0, bx, by, bz, ibx, iby, ibz, ax, ay, az);
        dm_vec4(xc, yc, zc, lfi1, bx, by, bz, ibx, iby, ibz, bx2, by2, bz2);
        float inv0 = 1.0f / (lfd0 + 1e-16f);
        float inv1 = 1.0f / (lfd1 + 1e-16f);
        float r0x = ax * inv0,  r0y = ay * inv0,  r0z = az * inv0;
        float r1x = bx2 * inv1, r1y = by2 * inv1, r1z = bz2 * inv1;

        float dot = r0x * r1x + r0y * r1y + r0z * r1z;
        float v2x = r1x - dot * r0x, v2y = r1y - dot * r0y, v2z = r1z - dot * r0z;
        float n2 = sqrtf(v2x * v2x + v2y * v2y + v2z * v2z);
        v2x /= n2; v2y /= n2; v2z /= n2;
        float v3x = r0y * r1z - r0z * r1y;
        float v3y = r0z * r1x - r0x * r1z;
        float v3z = r0x * r1y - r0y * r1x;
        float n3 = sqrtf(v3x * v3x + v3y * v3y + v3z * v3z);
        v3x /= n3; v3y /= n3; v3z /= n3;

        sA[a][0] = r0x; sA[a][1] = r0y; sA[a][2] = r0z;
        sA[a][3] = v2x; sA[a][4] = v2y; sA[a][5] = v2z;
        sA[a][6] = v3x; sA[a][7] = v3y; sA[a][8] = v3z;
    }
    __syncthreads();

    {
        int a = tid >> 6, s = tid & 63;
        if (s < 2 * ASEL) {
            float xc = cx[a], yc = cy[a], zc = cz[a];
            float* dsc = g_desc + (size_t)ci[a] * DD;
            unsigned long long key = (s < ASEL) ? sb[a][0][s] : sb[a][1][s - ASEL];
            float ad = key_dist(key);
            int   j  = key_idx(key);
            float vx, vy, vz;
            dm_vec4(xc, yc, zc, j, bx, by, bz, ibx, iby, ibz, vx, vy, vz);
            float inv = 1.0f / (ad + 1e-16f);
            float nx = vx * inv, ny = vy * inv, nz = vz * inv;
            #pragma unroll
            for (int r = 0; r < 3; r++) {
                float val = (sA[a][3 * r + 0] * nx + sA[a][3 * r + 1] * ny + sA[a][3 * r + 2] * nz) * inv;
                dsc[2 * SEL + s * 3 + r] = val;
            }
        }
    }

    // ---- weight-split tail ----
    {
        int gidx = blk * 256 + tid;
        if (gidx < 2 * DD * H) {
            int t = gidx / (DD * H);
            int r = gidx % (DD * H);
            int k = r / H, n = r % H;
            float v = w1[gidx];
            __nv_bfloat16 hi = __float2bfloat16(v);
            __nv_bfloat16 lo = __float2bfloat16(v - __bfloat162float(hi));
            size_t dst = ((size_t)(t * NC1 + (k >> 4)) * H + n) * 16 + (k & 15);
            g_w1h[dst] = hi; g_w1l[dst] = lo;
        }
        if (gidx < 2 * H * H) {
            int t = gidx >> 16;
            int k = (gidx >> 8) & 255, n = gidx & 255;
            size_t dst = ((size_t)(t * NC2 + (k >> 4)) * H + n) * 16 + (k & 15);
            float v2 = w2[gidx];
            __nv_bfloat16 h2 = __float2bfloat16(v2);
            g_w2h[dst] = h2; g_w2l[dst] = __float2bfloat16(v2 - __bfloat162float(h2));
            float v3 = w3[gidx];
            __nv_bfloat16 h3 = __float2bfloat16(v3);
            g_w3h[dst] = h3; g_w3l[dst] = __float2bfloat16(v3 - __bfloat162float(h3));
        }
    }
}

// ---------------- tensor-core MLP: warp-autonomous weight streaming (R16) ----------------
#define SMB_ALO 23040
#define SMB_W   46080
#define WSTG    16384
#define SMB_GI  111616
#define SMB_ES  111744
#define SM_TOTAL 111872

template<int NC, int AS>
__device__ __forceinline__ void do_layer(const __nv_bfloat16* __restrict__ gWh,
                                         const __nv_bfloat16* __restrict__ gWl,
                                         const float* __restrict__ bias,
                                         __nv_bfloat16* Ahi, __nv_bfloat16* Alo,
                                         uint32_t wring, int tid) {
    const int lane = tid & 31, wid = tid >> 5;
    const int n0 = wid * 16;

    float d[4][4];
    #pragma unroll
    for (int f = 0; f < 4; f++)
        #pragma unroll
        for (int e = 0; e < 4; e++) d[f][e] = 0.0f;

    const int arow  = lane & 15;
    const int akoff = (lane >> 4) * 8;
    const int b_r   = (lane & 7) + ((lane >> 4) << 3);
    const int kbit  = (lane >> 3) & 1;

    const uint32_t wreg = wring + wid * 1024;
    const uint32_t wdst = swz16((uint32_t)lane) * 16;
    const int  wrow = n0 + (lane >> 1), wpart = lane & 1;

    #pragma unroll
    for (int pc = 0; pc < 3; pc++) {
        uint32_t dst = wreg + pc * WSTG + wdst;
        cp16(dst,       gWh + ((size_t)pc * H + wrow) * 16 + wpart * 8);
        cp16(dst + 512, gWl + ((size_t)pc * H + wrow) * 16 + wpart * 8);
        cp_commit();
    }

    for (int c = 0; c < NC; c++) {
        cp_wait2();
        __syncwarp();

        int ch = c + 3;
        if (ch < NC) {
            uint32_t dst = wreg + (ch & 3) * WSTG + wdst;
            cp16(dst,       gWh + ((size_t)ch * H + wrow) * 16 + wpart * 8);
            cp16(dst + 512, gWl + ((size_t)ch * H + wrow) * 16 + wpart * 8);
        }
        cp_commit();

        const uint32_t stg = wreg + (c & 3) * WSTG;

        uint32_t ah0[4], al0[4], ah1[4], al1[4];
        ldsm4(ah0, Ahi + arow * AS + c * 16 + akoff);
        ldsm4(al0, Alo + arow * AS + c * 16 + akoff);
        ldsm4(ah1, Ahi + (16 + arow) * AS + c * 16 + akoff);
        ldsm4(al1, Alo + (16 + arow) * AS + c * 16 + akoff);

        uint32_t u = (uint32_t)(b_r * 2 + kbit);
        uint32_t baddr = stg + swz16(u) * 16;
        uint32_t bh[4], bl[4];
        ldsm4a(bh, baddr);
        ldsm4a(bl, baddr + 512);

        mma_bf16s(d[0], ah0, bh[0], bh[1]);
        mma_bf16s(d[0], ah0, bl[0], bl[1]);
        mma_bf16s(d[0], al0, bh[0], bh[1]);
        mma_bf16s(d[1], ah0, bh[2], bh[3]);
        mma_bf16s(d[1], ah0, bl[2], bl[3]);
        mma_bf16s(d[1], al0, bh[2], bh[3]);
        mma_bf16s(d[2], ah1, bh[0], bh[1]);
        mma_bf16s(d[2], ah1, bl[0], bl[1]);
        mma_bf16s(d[2], al1, bh[0], bh[1]);
        mma_bf16s(d[3], ah1, bh[2], bh[3]);
        mma_bf16s(d[3], ah1, bl[2], bl[3]);
        mma_bf16s(d[3], al1, bh[2], bh[3]);
    }
    cp_wait0();
    __syncwarp();
    __syncthreads();

    #pragma unroll
    for (int mh = 0; mh < 2; mh++) {
        #pragma unroll
        for (int nf = 0; nf < 2; nf++) {
            int m0 = mh * 16 + (lane >> 2);
            int n  = n0 + nf * 8 + (lane & 3) * 2;
            float b0 = bias[n], b1 = bias[n + 1];
            float (&dd)[4] = d[mh * 2 + nf];
            split_store(Ahi, Alo, m0,     n, tanh_fast(dd[0] + b0), tanh_fast(dd[1] + b1));
            split_store(Ahi, Alo, m0 + 8, n, tanh_fast(dd[2] + b0), tanh_fast(dd[3] + b1));
        }
    }
    __syncthreads();
}

__global__ void __launch_bounds__(512) k_mlp(const float* __restrict__ b1,
                                             const float* __restrict__ b2,
                                             const float* __restrict__ b3,
                                             const float* __restrict__ w4,
                                             const float* __restrict__ b4,
                                             float* __restrict__ out) {
    extern __shared__ char smem[];
    __nv_bfloat16* Ahi = (__nv_bfloat16*)(smem);
    __nv_bfloat16* Alo = (__nv_bfloat16*)(smem + SMB_ALO);
    uint32_t wring = smem_u32(smem + SMB_W);
    int*   gi = (int*)(smem + SMB_GI);
    float* es = (float*)(smem + SMB_ES);

    const int b    = blockIdx.x;
    const int t    = b / TPT;
    const int tile = b % TPT;
    const int cnt  = g_cnt[t];
    const int base = tile * 32;
    const int tid  = threadIdx.x;
    const int lane = tid & 31, wid = tid >> 5;
    const bool active = (base < cnt);

    float block_sum = 0.0f;

    if (active) {
        if (tid < 32) {
            int idx = base + tid;
            gi[tid] = (idx < cnt) ? g_list[t * NATOMS + idx] : -1;
            es[tid] = 0.0f;
        }
        __syncthreads();

        for (int idx = tid; idx < 32 * DD; idx += 512) {
            int m = idx / DD, k = idx % DD;
            float v = (gi[m] >= 0) ? g_desc[(size_t)gi[m] * DD + k] : 0.0f;
            __nv_bfloat16 hi = __float2bfloat16(v);
            Ahi[m * 360 + k] = hi;
            Alo[m * 360 + k] = __float2bfloat16(v - __bfloat162float(hi));
        }
        __syncthreads();

        do_layer<NC1, 360>(g_w1h + (size_t)t * NC1 * H * 16, g_w1l + (size_t)t * NC1 * H * 16,
                           b1 + t * H, Ahi, Alo, wring, tid);
        do_layer<NC2, 264>(g_w2h + (size_t)t * NC2 * H * 16, g_w2l + (size_t)t * NC2 * H * 16,
                           b2 + t * H, Ahi, Alo, wring, tid);
        do_layer<NC2, 264>(g_w3h + (size_t)t * NC2 * H * 16, g_w3l + (size_t)t * NC2 * H * 16,
                           b3 + t * H, Ahi, Alo, wring, tid);

        #pragma unroll
        for (int a = 0; a < 2; a++) {
            int m = wid * 2 + a;
            float s = 0.0f;
            #pragma unroll
            for (int c = 0; c < H / 32; c++) {
                int n = c * 32 + lane;
                float h = __bfloat162float(Ahi[m * 264 + n]) + __bfloat162float(Alo[m * 264 + n]);
                s += h * w4[t * H + n];
            }
            #pragma unroll
            for (int o = 16; o; o >>= 1) s += __shfl_down_sync(0xFFFFFFFFu, s, o);
            if (lane == 0 && gi[m] >= 0) es[m] = s + b4[t];
        }
        __syncthreads();

        if (wid == 0) {
            float s = es[lane];
            #pragma unroll
            for (int o = 16; o; o >>= 1) s += __shfl_down_sync(0xFFFFFFFFu, s, o);
            block_sum = s;
        }
    }

    if (tid == 0) {
        g_bsum[b] = block_sum;
        __threadfence();
        int old = atomicAdd(&g_done, 1);
        if (old == NBLK - 1) {
            float s = 0.0f;
            for (int k2 = 0; k2 < NBLK; k2++) s += g_bsum[k2];
            out[0] = s;
            g_done = 0;
            // reset counters for next graph replay
            g_cnt[0] = 0; g_cnt[1] = 0;
            for (int q = 0; q < ZBINS; q++) g_zcnt[q] = 0;
            for (int q = 0; q < NATOMS / 32; q++) g_typemask[q] = 0;
        }
    }
}

// ---------------- launch ----------------
extern "C" void kernel_launch(void* const* d_in, const int* in_sizes, int n_in,
                              void* d_out, int out_size) {
    const float* xyz   = (const float*)d_in[0];
    const float* box   = (const float*)d_in[1];
    const int*   types = (const int*)  d_in[2];
    const float* w1 = (const float*)d_in[3];
    const float* b1 = (const float*)d_in[4];
    const float* w2 = (const float*)d_in[5];
    const float* b2 = (const float*)d_in[6];
    const float* w3 = (const float*)d_in[7];
    const float* b3 = (const float*)d_in[8];
    const float* w4 = (const float*)d_in[9];
    const float* b4 = (const float*)d_in[10];

    cudaFuncSetAttribute(k_mlp, cudaFuncAttributeMaxDynamicSharedMemorySize, SM_TOTAL);

    k_binA <<<16, 256>>>(types, xyz);
    k_binB <<<1, 1024>>>();
    k_desc <<<NATOMS / 4, 256>>>(box, w1, w2, w3);
    k_mlp  <<<NBLK, 512, SM_TOTAL>>>(b1, b2, b3, w4, b4, (float*)d_out);
}